// round 7
// baseline (speedup 1.0000x reference)
#include <cuda_runtime.h>
#include <cuda_fp16.h>
#include <math_constants.h>
#include <cstdint>

// VQ-VAE Quantize on GB300 — Round 6:
//   mma.sync m16n8k16 fp16 (3-term split, fp32 acc) + top-2 margin + exact rescue.
//   R6: fused/coalesced prep (k_prepB), in-kernel A build, ldsm fragment pipelining.

#define NS    16384
#define DD    128
#define NC    10000
#define NT    79               // N tiles of 128 (padded to 10112)
#define PADK  392              // padded K row (fp16 elems) -> 784 B rows
#define ROWB  784
#define NOUT  (NS * DD)
#define NBLK  (NOUT / 256)
#define MARGIN 0.02f

#define A_BYTES  (128 * ROWB)      // 100352
#define BH_BYTES (64 * ROWB)       // 50176 (half tile: 64 codes)
#define SM_A   0
#define SM_B0  A_BYTES
#define SM_B1  (A_BYTES + BH_BYTES)
#define SM_MB  (A_BYTES + 2 * BH_BYTES)
#define SM_SZ  (SM_MB + 32)
#define SMEM_REQ   (SM_SZ + 1024)
#define SMEM_PREPB (128 * PADK * 2)     // 100352

__device__ __half  g_Be[(size_t)NT * 128 * PADK];   // B_ext tiles [J][PADK]
__device__ float   g_norms[NT * 128];               // exact ||c||^2 (+INF pads)
__device__ int     g_idx[NS];
__device__ int     g_flag[NS];
__device__ int     g_nflag;
__device__ double  g_partial[NBLK];

// ------------------------------------------------------------------ helpers
__device__ __forceinline__ uint32_t smem_u32(const void* p) {
    uint32_t a;
    asm("{ .reg .u64 t; cvta.to.shared.u64 t, %1; cvt.u32.u64 %0, t; }" : "=r"(a) : "l"(p));
    return a;
}
__device__ __forceinline__ void mbar_init(uint32_t mbar, uint32_t cnt) {
    asm volatile("mbarrier.init.shared.b64 [%0], %1;" :: "r"(mbar), "r"(cnt) : "memory");
}
__device__ __forceinline__ void mbar_expect_tx(uint32_t mbar, uint32_t bytes) {
    asm volatile("mbarrier.arrive.expect_tx.shared.b64 _, [%0], %1;"
                 :: "r"(mbar), "r"(bytes) : "memory");
}
__device__ __forceinline__ void mbar_arrive(uint32_t mbar) {
    asm volatile("mbarrier.arrive.shared.b64 _, [%0];" :: "r"(mbar) : "memory");
}
__device__ __forceinline__ void mbar_wait(uint32_t mbar, uint32_t parity) {
    asm volatile(
        "{\n\t.reg .pred P;\n"
        "W%=:\n\t"
        "mbarrier.try_wait.parity.acquire.cta.shared::cta.b64 P, [%0], %1, 0x989680;\n\t"
        "@P bra D%=;\n\t"
        "bra W%=;\n"
        "D%=:\n\t}"
        :: "r"(mbar), "r"(parity) : "memory");
}
__device__ __forceinline__ void bulk_g2s(uint32_t dst, const void* src, uint32_t bytes,
                                         uint32_t mbar) {
    asm volatile(
        "cp.async.bulk.shared::cluster.global.mbarrier::complete_tx::bytes [%0], [%1], %2, [%3];"
        :: "r"(dst), "l"(src), "r"(bytes), "r"(mbar) : "memory");
}
__device__ __forceinline__ void ldsm4(uint32_t& r0, uint32_t& r1, uint32_t& r2, uint32_t& r3,
                                      uint32_t addr) {
    asm volatile("ldmatrix.sync.aligned.m8n8.x4.shared.b16 {%0,%1,%2,%3}, [%4];"
                 : "=r"(r0), "=r"(r1), "=r"(r2), "=r"(r3) : "r"(addr));
}
__device__ __forceinline__ void mma16816(float& d0, float& d1, float& d2, float& d3,
                                         uint32_t a0, uint32_t a1, uint32_t a2, uint32_t a3,
                                         uint32_t b0, uint32_t b1) {
    asm volatile(
        "mma.sync.aligned.m16n8k16.row.col.f32.f16.f16.f32 "
        "{%0,%1,%2,%3}, {%4,%5,%6,%7}, {%8,%9}, {%0,%1,%2,%3};"
        : "+f"(d0), "+f"(d1), "+f"(d2), "+f"(d3)
        : "r"(a0), "r"(a1), "r"(a2), "r"(a3), "r"(b0), "r"(b1));
}

// ---------------------------------------------- fused B_ext build + norms
// One block per 128-code tile. Stage B_ext tile in smem (reads of C coalesced),
// then copy out as contiguous 16B chunks (writes coalesced). Norms fused.
__global__ __launch_bounds__(256, 1)
void k_prepB(const float* __restrict__ C) {
    extern __shared__ __half tile[];        // 128 * PADK halfs
    __shared__ float np[128];
    const int tid = threadIdx.x;
    const int T = blockIdx.x;
    const int j = tid & 127;
    const int half = tid >> 7;              // d range [half*64, half*64+64)
    const int J = T * 128 + j;
    const bool valid = (J < NC);

    if (T == 0 && tid == 0) g_nflag = 0;    // reset rescue list each replay

    float nrm = 0.f;
    __half* row = tile + j * PADK;
#pragma unroll 4
    for (int dd = 0; dd < 64; dd++) {
        const int d = half * 64 + dd;
        float c = valid ? C[(size_t)d * NC + J] : 0.f;   // coalesced across j
        nrm = fmaf(c, c, nrm);
        __half h = __float2half_rn(c);
        __half l = __float2half_rn(c - __half2float(h));
        row[d]       = h;
        row[128 + d] = l;
        row[256 + d] = h;
    }
    if (half == 1) np[j] = nrm;
    __syncthreads();
    if (half == 0)
        g_norms[J] = valid ? (nrm + np[j]) : CUDART_INF_F;

    // coalesced copy out: 128*PADK halfs = 6272 int4 chunks
    const int4* src = (const int4*)tile;
    int4* dst = (int4*)(g_Be + (size_t)T * 128 * PADK);
    for (int i = tid; i < (128 * PADK * 2) / 16; i += 256) dst[i] = src[i];
}

// --------------------------------------------------- main tensor-core kernel
// 128 CTAs x 288 threads. Warps 0-7 (4M x 2N over 128x64 half-tile, warp tile
// 32x32): mma consumers with 2-stage ldsm fragment pipeline. Thread 256: B producer.
__global__ __launch_bounds__(288, 1)
void k_argmin(const float* __restrict__ X) {
    extern __shared__ char sraw[];
    const uint32_t sb0 = smem_u32(sraw);
    const uint32_t sb  = (sb0 + 1023u) & ~1023u;
    char* s0 = sraw + (sb - sb0);
    const int tid = threadIdx.x;

    const uint32_t mbF0 = sb + SM_MB + 0;
    const uint32_t mbF1 = sb + SM_MB + 8;
    const uint32_t mbE0 = sb + SM_MB + 16;
    const uint32_t mbE1 = sb + SM_MB + 24;

    if (tid == 0) {
        mbar_init(mbF0, 1); mbar_init(mbF1, 1);
        mbar_init(mbE0, 1); mbar_init(mbE1, 1);
    }
    __syncthreads();

    if (tid == 256) {
        // ----------------------------- producer -----------------------------
        const char* be = (const char*)g_Be;
        for (int h = 0; h < 2 * NT; h++) {
            int buf = h & 1, ph = (h >> 1) & 1;
            mbar_wait(buf ? mbE1 : mbE0, ph ^ 1);   // first pass-through free
            uint32_t mf = buf ? mbF1 : mbF0;
            mbar_expect_tx(mf, BH_BYTES);
            bulk_g2s(sb + (buf ? SM_B1 : SM_B0),
                     be + (size_t)(h >> 1) * (128 * ROWB) + (size_t)buf * BH_BYTES,
                     BH_BYTES, mf);
        }
    } else if (tid < 256) {
        // ------------------- consumers: build A_ext in smem ------------------
        {
            const int row = tid >> 1;
            const int d0  = (tid & 1) * 64;
            const float* xr = X + (size_t)(blockIdx.x * 128 + row) * DD + d0;
            __half* arow = (__half*)(s0 + SM_A) + row * PADK;
#pragma unroll 4
            for (int d = 0; d < 64; d++) {
                float x = xr[d];
                __half h = __float2half_rn(x);
                __half l = __float2half_rn(x - __half2float(h));
                arow[d0 + d]       = h;
                arow[128 + d0 + d] = h;
                arow[256 + d0 + d] = l;
            }
        }
        asm volatile("bar.sync 1, 256;" ::: "memory");

        const int l   = tid & 31;
        const int wid = tid >> 5;
        const int wm  = wid & 3;       // m in [wm*32, wm*32+32)
        const int wn  = wid >> 2;      // n in [wn*32, wn*32+32) within 64-half

        const uint32_t rowA  = (uint32_t)(wm * 32 + ((l >> 3) & 1) * 8 + (l & 7));
        const uint32_t aoff  = (uint32_t)(((l >> 4) & 1) * 16);
        const uint32_t addrA = sb + SM_A + rowA * ROWB + aoff;
        const uint32_t rowBl = (uint32_t)(wn * 32 + ((l >> 4) & 1) * 8 + (l & 7));
        const uint32_t boff  = (uint32_t)(((l >> 3) & 1) * 16);

        float v1[4], v2[4]; int i1[4];
#pragma unroll
        for (int r = 0; r < 4; r++) { v1[r] = CUDART_INF_F; v2[r] = CUDART_INF_F; i1[r] = 0; }

        for (int h = 0; h < 2 * NT; h++) {
            const int buf = h & 1, ph = (h >> 1) & 1;
            const int tile = h >> 1, hb = h & 1;
            const uint32_t bbase = sb + (buf ? SM_B1 : SM_B0);
            mbar_wait(buf ? mbF1 : mbF0, ph);

            float acc[2][4][4];
#pragma unroll
            for (int sm = 0; sm < 2; sm++)
#pragma unroll
                for (int sn = 0; sn < 4; sn++)
#pragma unroll
                    for (int q = 0; q < 4; q++) acc[sm][sn][q] = 0.f;

            const uint32_t aA0 = addrA;
            const uint32_t aA1 = addrA + 16 * ROWB;
            const uint32_t aB0 = bbase + rowBl * ROWB + boff;
            const uint32_t aB1 = aB0 + 16 * ROWB;

            // 2-stage fragment pipeline: prefetch ks+1 while mma(ks) issues.
            uint32_t fa0[2][4], fa1[2][4], fb0[2][4], fb1[2][4];
            ldsm4(fa0[0][0], fa0[0][1], fa0[0][2], fa0[0][3], aA0);
            ldsm4(fa1[0][0], fa1[0][1], fa1[0][2], fa1[0][3], aA1);
            ldsm4(fb0[0][0], fb0[0][1], fb0[0][2], fb0[0][3], aB0);
            ldsm4(fb1[0][0], fb1[0][1], fb1[0][2], fb1[0][3], aB1);

#pragma unroll
            for (int ks = 0; ks < 24; ks++) {
                const int cu = ks & 1, nx = cu ^ 1;
                if (ks < 23) {
                    const uint32_t ko = (uint32_t)((ks + 1) * 32);
                    ldsm4(fa0[nx][0], fa0[nx][1], fa0[nx][2], fa0[nx][3], aA0 + ko);
                    ldsm4(fa1[nx][0], fa1[nx][1], fa1[nx][2], fa1[nx][3], aA1 + ko);
                    ldsm4(fb0[nx][0], fb0[nx][1], fb0[nx][2], fb0[nx][3], aB0 + ko);
                    ldsm4(fb1[nx][0], fb1[nx][1], fb1[nx][2], fb1[nx][3], aB1 + ko);
                }
                mma16816(acc[0][0][0], acc[0][0][1], acc[0][0][2], acc[0][0][3],
                         fa0[cu][0], fa0[cu][1], fa0[cu][2], fa0[cu][3], fb0[cu][0], fb0[cu][1]);
                mma16816(acc[0][1][0], acc[0][1][1], acc[0][1][2], acc[0][1][3],
                         fa0[cu][0], fa0[cu][1], fa0[cu][2], fa0[cu][3], fb0[cu][2], fb0[cu][3]);
                mma16816(acc[0][2][0], acc[0][2][1], acc[0][2][2], acc[0][2][3],
                         fa0[cu][0], fa0[cu][1], fa0[cu][2], fa0[cu][3], fb1[cu][0], fb1[cu][1]);
                mma16816(acc[0][3][0], acc[0][3][1], acc[0][3][2], acc[0][3][3],
                         fa0[cu][0], fa0[cu][1], fa0[cu][2], fa0[cu][3], fb1[cu][2], fb1[cu][3]);
                mma16816(acc[1][0][0], acc[1][0][1], acc[1][0][2], acc[1][0][3],
                         fa1[cu][0], fa1[cu][1], fa1[cu][2], fa1[cu][3], fb0[cu][0], fb0[cu][1]);
                mma16816(acc[1][1][0], acc[1][1][1], acc[1][1][2], acc[1][1][3],
                         fa1[cu][0], fa1[cu][1], fa1[cu][2], fa1[cu][3], fb0[cu][2], fb0[cu][3]);
                mma16816(acc[1][2][0], acc[1][2][1], acc[1][2][2], acc[1][2][3],
                         fa1[cu][0], fa1[cu][1], fa1[cu][2], fa1[cu][3], fb1[cu][0], fb1[cu][1]);
                mma16816(acc[1][3][0], acc[1][3][1], acc[1][3][2], acc[1][3][3],
                         fa1[cu][0], fa1[cu][1], fa1[cu][2], fa1[cu][3], fb1[cu][2], fb1[cu][3]);
            }

            asm volatile("bar.sync 1, 256;" ::: "memory");
            if (tid == 0) mbar_arrive(buf ? mbE1 : mbE0);

            // epilogue: dist = n_j - 2*acc ; per-thread top-2 per row-slot
            const int jg0 = tile * 128 + hb * 64 + wn * 32 + (l & 3) * 2;
#pragma unroll
            for (int sn = 0; sn < 4; sn++) {
                const int j0 = jg0 + sn * 8;
                const float2 nn = *(const float2*)(g_norms + j0);
#pragma unroll
                for (int sm = 0; sm < 2; sm++)
#pragma unroll
                    for (int rh = 0; rh < 2; rh++) {
                        const int slot = sm * 2 + rh;
                        float d0 = fmaf(-2.f, acc[sm][sn][rh * 2 + 0], nn.x);
                        float d1 = fmaf(-2.f, acc[sm][sn][rh * 2 + 1], nn.y);
                        if (d0 < v1[slot]) { v2[slot] = v1[slot]; v1[slot] = d0; i1[slot] = j0; }
                        else if (d0 < v2[slot]) v2[slot] = d0;
                        if (d1 < v1[slot]) { v2[slot] = v1[slot]; v1[slot] = d1; i1[slot] = j0 + 1; }
                        else if (d1 < v2[slot]) v2[slot] = d1;
                    }
            }
        }

        // stash per-thread top-2 into smem (A region is free now)
        asm volatile("bar.sync 1, 256;" ::: "memory");
        {
            float* sv1 = (float*)(s0 + SM_A);
            int*   si1 = (int*)(s0 + SM_A + 4096);
            float* sv2 = (float*)(s0 + SM_A + 8192);
            const int cidx = wn * 4 + (l & 3);
#pragma unroll
            for (int sm = 0; sm < 2; sm++)
#pragma unroll
                for (int rh = 0; rh < 2; rh++) {
                    const int slot = sm * 2 + rh;
                    const int row = wm * 32 + sm * 16 + rh * 8 + (l >> 2);
                    sv1[row * 8 + cidx] = v1[slot];
                    si1[row * 8 + cidx] = i1[slot];
                    sv2[row * 8 + cidx] = v2[slot];
                }
        }
        asm volatile("bar.sync 1, 256;" ::: "memory");

        if (tid < 128) {
            float* sv1 = (float*)(s0 + SM_A);
            int*   si1 = (int*)(s0 + SM_A + 4096);
            float* sv2 = (float*)(s0 + SM_A + 8192);
            float b1 = CUDART_INF_F, b2 = CUDART_INF_F; int bi = 0;
#pragma unroll
            for (int u = 0; u < 8; u++) {
                float e1 = sv1[tid * 8 + u];
                int   ei = si1[tid * 8 + u];
                float e2 = sv2[tid * 8 + u];
                if (e1 < b1 || (e1 == b1 && ei < bi)) {
                    b2 = fminf(b1, e2); b1 = e1; bi = ei;
                } else {
                    b2 = fminf(b2, e1);
                }
            }
            const int grow = blockIdx.x * 128 + tid;
            g_idx[grow] = bi;
            if (b2 - b1 <= MARGIN) {
                int pos = atomicAdd(&g_nflag, 1);
                if (pos < NS) g_flag[pos] = grow;
            }
        }
    }
}

// ------------------------------------------ exact fp32 rescue for tight rows
__global__ void k_rescue(const float* __restrict__ X, const float* __restrict__ C) {
    __shared__ float xs[DD];
    __shared__ float bv[128];
    __shared__ int   bix[128];
    const int n = g_nflag;
    for (int idx = blockIdx.x; idx < n && idx < NS; idx += gridDim.x) {
        const int row = g_flag[idx];
        if (threadIdx.x < DD) xs[threadIdx.x] = X[(size_t)row * DD + threadIdx.x];
        __syncthreads();
        float best = CUDART_INF_F; int bj = 0;
        for (int j = threadIdx.x; j < NC; j += 128) {
            float dot = 0.f;
#pragma unroll 8
            for (int d = 0; d < DD; d++)
                dot = fmaf(xs[d], C[(size_t)d * NC + j], dot);
            float v = fmaf(-2.f, dot, g_norms[j]);
            if (v < best) { best = v; bj = j; }
        }
        bv[threadIdx.x] = best; bix[threadIdx.x] = bj;
        __syncthreads();
        if (threadIdx.x == 0) {
            float b = bv[0]; int bi = bix[0];
            for (int u = 1; u < 128; u++) {
                float v = bv[u]; int ix = bix[u];
                if (v < b || (v == b && ix < bi)) { b = v; bi = ix; }
            }
            g_idx[row] = bi;
        }
        __syncthreads();
    }
}

// ------------------------------------- gather + straight-through + loss parts
__global__ void k_gather(const float* __restrict__ X, const float* __restrict__ C,
                         float* __restrict__ out) {
    int t = blockIdx.x * 256 + threadIdx.x;
    int i = t >> 7;
    int d = t & 127;
    int j = g_idx[i];
    float x = X[t];
    float q = C[(size_t)d * NC + j];
    out[t] = x + (q - x);
    float diff = q - x;
    float v = diff * diff;
#pragma unroll
    for (int off = 16; off > 0; off >>= 1)
        v += __shfl_down_sync(0xffffffffu, v, off);
    __shared__ float ws[8];
    int lane = threadIdx.x & 31, w = threadIdx.x >> 5;
    if (lane == 0) ws[w] = v;
    __syncthreads();
    if (threadIdx.x == 0) {
        double s = 0.0;
        for (int k = 0; k < 8; k++) s += (double)ws[k];
        g_partial[blockIdx.x] = s;
    }
}

__global__ void k_loss(float* __restrict__ out, int loss_pos) {
    __shared__ double sm[256];
    double s = 0.0;
    for (int k = threadIdx.x; k < NBLK; k += 256) s += g_partial[k];
    sm[threadIdx.x] = s;
    __syncthreads();
    for (int off = 128; off > 0; off >>= 1) {
        if (threadIdx.x < off) sm[threadIdx.x] += sm[threadIdx.x + off];
        __syncthreads();
    }
    if (threadIdx.x == 0 && loss_pos >= 0)
        out[loss_pos] = (float)(1.25 * sm[0] / (double)NOUT);
}

// ---------------------------------------------------------------------- entry
extern "C" void kernel_launch(void* const* d_in, const int* in_sizes, int n_in,
                              void* d_out, int out_size) {
    const float* X = (const float*)d_in[0];
    const float* C = (const float*)d_in[1];
    if (n_in >= 2 && in_sizes[0] == DD * NC && in_sizes[1] == NOUT) {
        const float* tmp = X; X = C; C = tmp;
    }
    float* out = (float*)d_out;

    static int smem_set = 0;
    if (!smem_set) {
        cudaFuncSetAttribute(k_argmin, cudaFuncAttributeMaxDynamicSharedMemorySize,
                             SMEM_REQ);
        cudaFuncSetAttribute(k_prepB, cudaFuncAttributeMaxDynamicSharedMemorySize,
                             SMEM_PREPB);
        smem_set = 1;
    }

    k_prepB<<<NT, 256, SMEM_PREPB>>>(C);
    k_argmin<<<128, 288, SMEM_REQ>>>(X);
    k_rescue<<<128, 128>>>(X, C);
    k_gather<<<NBLK, 256>>>(X, C, out);

    int loss_pos = (out_size > NOUT) ? (out_size - 1) : -1;
    k_loss<<<1, 256>>>(out, loss_pos);
}

// round 9
// speedup vs baseline: 1.0216x; 1.0216x over previous
#include <cuda_runtime.h>
#include <cuda_fp16.h>
#include <math_constants.h>
#include <cstdint>

// VQ-VAE Quantize on GB300 — Round 7:
//   mma.sync m16n8k16 fp16 (3-term split, fp32 acc) + top-2 margin + exact rescue.
//   R7: 16 consumer warps (4Mx4N, warp tile 32x16), single-stage fragments.

#define NS    16384
#define DD    128
#define NC    10000
#define NT    79               // N tiles of 128 (padded to 10112)
#define PADK  392              // padded K row (fp16 elems) -> 784 B rows
#define ROWB  784
#define NOUT  (NS * DD)
#define NBLK  (NOUT / 256)
#define MARGIN 0.02f

#define A_BYTES  (128 * ROWB)      // 100352
#define BH_BYTES (64 * ROWB)       // 50176 (half tile: 64 codes)
#define SM_A   0
#define SM_B0  A_BYTES
#define SM_B1  (A_BYTES + BH_BYTES)
#define SM_MB  (A_BYTES + 2 * BH_BYTES)
#define SM_SZ  (SM_MB + 32)
#define SMEM_REQ   (SM_SZ + 1024)
#define SMEM_PREPB (128 * PADK * 2)     // 100352

#define NTHR  544              // 16 consumer warps + 1 producer warp

__device__ __half  g_Be[(size_t)NT * 128 * PADK];   // B_ext tiles [J][PADK]
__device__ float   g_norms[NT * 128];               // exact ||c||^2 (+INF pads)
__device__ int     g_idx[NS];
__device__ int     g_flag[NS];
__device__ int     g_nflag;
__device__ double  g_partial[NBLK];

// ------------------------------------------------------------------ helpers
__device__ __forceinline__ uint32_t smem_u32(const void* p) {
    uint32_t a;
    asm("{ .reg .u64 t; cvta.to.shared.u64 t, %1; cvt.u32.u64 %0, t; }" : "=r"(a) : "l"(p));
    return a;
}
__device__ __forceinline__ void mbar_init(uint32_t mbar, uint32_t cnt) {
    asm volatile("mbarrier.init.shared.b64 [%0], %1;" :: "r"(mbar), "r"(cnt) : "memory");
}
__device__ __forceinline__ void mbar_expect_tx(uint32_t mbar, uint32_t bytes) {
    asm volatile("mbarrier.arrive.expect_tx.shared.b64 _, [%0], %1;"
                 :: "r"(mbar), "r"(bytes) : "memory");
}
__device__ __forceinline__ void mbar_arrive(uint32_t mbar) {
    asm volatile("mbarrier.arrive.shared.b64 _, [%0];" :: "r"(mbar) : "memory");
}
__device__ __forceinline__ void mbar_wait(uint32_t mbar, uint32_t parity) {
    asm volatile(
        "{\n\t.reg .pred P;\n"
        "W%=:\n\t"
        "mbarrier.try_wait.parity.acquire.cta.shared::cta.b64 P, [%0], %1, 0x989680;\n\t"
        "@P bra D%=;\n\t"
        "bra W%=;\n"
        "D%=:\n\t}"
        :: "r"(mbar), "r"(parity) : "memory");
}
__device__ __forceinline__ void bulk_g2s(uint32_t dst, const void* src, uint32_t bytes,
                                         uint32_t mbar) {
    asm volatile(
        "cp.async.bulk.shared::cluster.global.mbarrier::complete_tx::bytes [%0], [%1], %2, [%3];"
        :: "r"(dst), "l"(src), "r"(bytes), "r"(mbar) : "memory");
}
__device__ __forceinline__ void ldsm4(uint32_t& r0, uint32_t& r1, uint32_t& r2, uint32_t& r3,
                                      uint32_t addr) {
    asm volatile("ldmatrix.sync.aligned.m8n8.x4.shared.b16 {%0,%1,%2,%3}, [%4];"
                 : "=r"(r0), "=r"(r1), "=r"(r2), "=r"(r3) : "r"(addr));
}
__device__ __forceinline__ void mma16816(float& d0, float& d1, float& d2, float& d3,
                                         uint32_t a0, uint32_t a1, uint32_t a2, uint32_t a3,
                                         uint32_t b0, uint32_t b1) {
    asm volatile(
        "mma.sync.aligned.m16n8k16.row.col.f32.f16.f16.f32 "
        "{%0,%1,%2,%3}, {%4,%5,%6,%7}, {%8,%9}, {%0,%1,%2,%3};"
        : "+f"(d0), "+f"(d1), "+f"(d2), "+f"(d3)
        : "r"(a0), "r"(a1), "r"(a2), "r"(a3), "r"(b0), "r"(b1));
}

// ---------------------------------------------- fused B_ext build + norms
__global__ __launch_bounds__(256, 1)
void k_prepB(const float* __restrict__ C) {
    extern __shared__ __half tile[];        // 128 * PADK halfs
    __shared__ float np[128];
    const int tid = threadIdx.x;
    const int T = blockIdx.x;
    const int j = tid & 127;
    const int half = tid >> 7;              // d range [half*64, half*64+64)
    const int J = T * 128 + j;
    const bool valid = (J < NC);

    if (T == 0 && tid == 0) g_nflag = 0;    // reset rescue list each replay

    float nrm = 0.f;
    __half* row = tile + j * PADK;
#pragma unroll 4
    for (int dd = 0; dd < 64; dd++) {
        const int d = half * 64 + dd;
        float c = valid ? C[(size_t)d * NC + J] : 0.f;   // coalesced across j
        nrm = fmaf(c, c, nrm);
        __half h = __float2half_rn(c);
        __half l = __float2half_rn(c - __half2float(h));
        row[d]       = h;
        row[128 + d] = l;
        row[256 + d] = h;
    }
    if (half == 1) np[j] = nrm;
    __syncthreads();
    if (half == 0)
        g_norms[J] = valid ? (nrm + np[j]) : CUDART_INF_F;

    const int4* src = (const int4*)tile;
    int4* dst = (int4*)(g_Be + (size_t)T * 128 * PADK);
    for (int i = tid; i < (128 * PADK * 2) / 16; i += 256) dst[i] = src[i];
}

// --------------------------------------------------- main tensor-core kernel
// 128 CTAs x 544 threads. Warps 0-15: consumers over 128x64 half-tile
// (wm = wid&3 -> 32 m-rows, wn = wid>>2 -> 16 n-cols). Thread 512: producer.
__global__ __launch_bounds__(NTHR, 1)
void k_argmin(const float* __restrict__ X) {
    extern __shared__ char sraw[];
    const uint32_t sb0 = smem_u32(sraw);
    const uint32_t sb  = (sb0 + 1023u) & ~1023u;
    char* s0 = sraw + (sb - sb0);
    const int tid = threadIdx.x;

    const uint32_t mbF0 = sb + SM_MB + 0;
    const uint32_t mbF1 = sb + SM_MB + 8;
    const uint32_t mbE0 = sb + SM_MB + 16;
    const uint32_t mbE1 = sb + SM_MB + 24;

    if (tid == 0) {
        mbar_init(mbF0, 1); mbar_init(mbF1, 1);
        mbar_init(mbE0, 1); mbar_init(mbE1, 1);
    }
    __syncthreads();

    if (tid >= 512) {
        // ----------------------------- producer -----------------------------
        if (tid == 512) {
            const char* be = (const char*)g_Be;
            for (int h = 0; h < 2 * NT; h++) {
                int buf = h & 1, ph = (h >> 1) & 1;
                mbar_wait(buf ? mbE1 : mbE0, ph ^ 1);   // first pass free
                uint32_t mf = buf ? mbF1 : mbF0;
                mbar_expect_tx(mf, BH_BYTES);
                bulk_g2s(sb + (buf ? SM_B1 : SM_B0),
                         be + (size_t)(h >> 1) * (128 * ROWB) + (size_t)buf * BH_BYTES,
                         BH_BYTES, mf);
            }
        }
    } else {
        // ------------------- consumers: build A_ext in smem ------------------
        {
            const int row = tid >> 2;
            const int d0  = (tid & 3) * 32;
            const float* xr = X + (size_t)(blockIdx.x * 128 + row) * DD + d0;
            __half* arow = (__half*)(s0 + SM_A) + row * PADK;
#pragma unroll
            for (int q = 0; q < 8; q++) {
                float4 v = *(const float4*)(xr + q * 4);
                float xv[4] = {v.x, v.y, v.z, v.w};
#pragma unroll
                for (int u = 0; u < 4; u++) {
                    const int d = d0 + q * 4 + u;
                    __half h = __float2half_rn(xv[u]);
                    __half l = __float2half_rn(xv[u] - __half2float(h));
                    arow[d]       = h;
                    arow[128 + d] = h;
                    arow[256 + d] = l;
                }
            }
        }
        asm volatile("bar.sync 1, 512;" ::: "memory");

        const int l   = tid & 31;
        const int wid = tid >> 5;
        const int wm  = wid & 3;       // m in [wm*32, wm*32+32)
        const int wn  = wid >> 2;      // n in [wn*16, wn*16+16) within 64-half

        const uint32_t rowA  = (uint32_t)(wm * 32 + ((l >> 3) & 1) * 8 + (l & 7));
        const uint32_t aoff  = (uint32_t)(((l >> 4) & 1) * 16);
        const uint32_t addrA = sb + SM_A + rowA * ROWB + aoff;
        const uint32_t rowBl = (uint32_t)(wn * 16 + ((l >> 4) & 1) * 8 + (l & 7));
        const uint32_t boff  = (uint32_t)(((l >> 3) & 1) * 16);

        float v1[4], v2[4]; int i1[4];
#pragma unroll
        for (int r = 0; r < 4; r++) { v1[r] = CUDART_INF_F; v2[r] = CUDART_INF_F; i1[r] = 0; }

        for (int h = 0; h < 2 * NT; h++) {
            const int buf = h & 1, ph = (h >> 1) & 1;
            const int tile = h >> 1, hb = h & 1;
            const uint32_t bbase = sb + (buf ? SM_B1 : SM_B0);
            mbar_wait(buf ? mbF1 : mbF0, ph);

            float acc[2][2][4];
#pragma unroll
            for (int mf = 0; mf < 2; mf++)
#pragma unroll
                for (int nf = 0; nf < 2; nf++)
#pragma unroll
                    for (int q = 0; q < 4; q++) acc[mf][nf][q] = 0.f;

            const uint32_t aA0 = addrA;
            const uint32_t aA1 = addrA + 16 * ROWB;
            const uint32_t aB  = bbase + rowBl * ROWB + boff;

#pragma unroll
            for (int ks = 0; ks < 24; ks++) {
                const uint32_t ko = (uint32_t)(ks * 32);
                uint32_t a0[4], a1[4], b[4];
                ldsm4(a0[0], a0[1], a0[2], a0[3], aA0 + ko);
                ldsm4(a1[0], a1[1], a1[2], a1[3], aA1 + ko);
                ldsm4(b[0], b[1], b[2], b[3], aB + ko);
                mma16816(acc[0][0][0], acc[0][0][1], acc[0][0][2], acc[0][0][3],
                         a0[0], a0[1], a0[2], a0[3], b[0], b[1]);
                mma16816(acc[0][1][0], acc[0][1][1], acc[0][1][2], acc[0][1][3],
                         a0[0], a0[1], a0[2], a0[3], b[2], b[3]);
                mma16816(acc[1][0][0], acc[1][0][1], acc[1][0][2], acc[1][0][3],
                         a1[0], a1[1], a1[2], a1[3], b[0], b[1]);
                mma16816(acc[1][1][0], acc[1][1][1], acc[1][1][2], acc[1][1][3],
                         a1[0], a1[1], a1[2], a1[3], b[2], b[3]);
            }

            asm volatile("bar.sync 1, 512;" ::: "memory");
            if (tid == 0) mbar_arrive(buf ? mbE1 : mbE0);

            // epilogue: dist = n_j - 2*acc ; per-thread top-2 per row-slot
            const int jg0 = tile * 128 + hb * 64 + wn * 16 + (l & 3) * 2;
#pragma unroll
            for (int nf = 0; nf < 2; nf++) {
                const int j0 = jg0 + nf * 8;
                const float2 nn = *(const float2*)(g_norms + j0);
#pragma unroll
                for (int mf = 0; mf < 2; mf++)
#pragma unroll
                    for (int rh = 0; rh < 2; rh++) {
                        const int slot = mf * 2 + rh;
                        float d0 = fmaf(-2.f, acc[mf][nf][rh * 2 + 0], nn.x);
                        float d1 = fmaf(-2.f, acc[mf][nf][rh * 2 + 1], nn.y);
                        if (d0 < v1[slot]) { v2[slot] = v1[slot]; v1[slot] = d0; i1[slot] = j0; }
                        else if (d0 < v2[slot]) v2[slot] = d0;
                        if (d1 < v1[slot]) { v2[slot] = v1[slot]; v1[slot] = d1; i1[slot] = j0 + 1; }
                        else if (d1 < v2[slot]) v2[slot] = d1;
                    }
            }
        }

        // stash per-thread top-2 into smem (A region free now): 16 cands/row
        asm volatile("bar.sync 1, 512;" ::: "memory");
        {
            float* sv1 = (float*)(s0 + SM_A);
            int*   si1 = (int*)(s0 + SM_A + 8192);
            float* sv2 = (float*)(s0 + SM_A + 16384);
            const int cidx = wn * 4 + (l & 3);
#pragma unroll
            for (int mf = 0; mf < 2; mf++)
#pragma unroll
                for (int rh = 0; rh < 2; rh++) {
                    const int slot = mf * 2 + rh;
                    const int row = wm * 32 + mf * 16 + rh * 8 + (l >> 2);
                    sv1[row * 16 + cidx] = v1[slot];
                    si1[row * 16 + cidx] = i1[slot];
                    sv2[row * 16 + cidx] = v2[slot];
                }
        }
        asm volatile("bar.sync 1, 512;" ::: "memory");

        if (tid < 128) {
            float* sv1 = (float*)(s0 + SM_A);
            int*   si1 = (int*)(s0 + SM_A + 8192);
            float* sv2 = (float*)(s0 + SM_A + 16384);
            float b1 = CUDART_INF_F, b2 = CUDART_INF_F; int bi = 0;
#pragma unroll
            for (int u = 0; u < 16; u++) {
                float e1 = sv1[tid * 16 + u];
                int   ei = si1[tid * 16 + u];
                float e2 = sv2[tid * 16 + u];
                if (e1 < b1 || (e1 == b1 && ei < bi)) {
                    b2 = fminf(b1, e2); b1 = e1; bi = ei;
                } else {
                    b2 = fminf(b2, e1);
                }
            }
            const int grow = blockIdx.x * 128 + tid;
            g_idx[grow] = bi;
            if (b2 - b1 <= MARGIN) {
                int pos = atomicAdd(&g_nflag, 1);
                if (pos < NS) g_flag[pos] = grow;
            }
        }
    }
}

// ------------------------------------------ exact fp32 rescue for tight rows
__global__ void k_rescue(const float* __restrict__ X, const float* __restrict__ C) {
    __shared__ float xs[DD];
    __shared__ float bv[128];
    __shared__ int   bix[128];
    const int n = g_nflag;
    for (int idx = blockIdx.x; idx < n && idx < NS; idx += gridDim.x) {
        const int row = g_flag[idx];
        if (threadIdx.x < DD) xs[threadIdx.x] = X[(size_t)row * DD + threadIdx.x];
        __syncthreads();
        float best = CUDART_INF_F; int bj = 0;
        for (int j = threadIdx.x; j < NC; j += 128) {
            float dot = 0.f;
#pragma unroll 8
            for (int d = 0; d < DD; d++)
                dot = fmaf(xs[d], C[(size_t)d * NC + j], dot);
            float v = fmaf(-2.f, dot, g_norms[j]);
            if (v < best) { best = v; bj = j; }
        }
        bv[threadIdx.x] = best; bix[threadIdx.x] = bj;
        __syncthreads();
        if (threadIdx.x == 0) {
            float b = bv[0]; int bi = bix[0];
            for (int u = 1; u < 128; u++) {
                float v = bv[u]; int ix = bix[u];
                if (v < b || (v == b && ix < bi)) { b = v; bi = ix; }
            }
            g_idx[row] = bi;
        }
        __syncthreads();
    }
}

// ------------------------------------- gather + straight-through + loss parts
__global__ void k_gather(const float* __restrict__ X, const float* __restrict__ C,
                         float* __restrict__ out) {
    int t = blockIdx.x * 256 + threadIdx.x;
    int i = t >> 7;
    int d = t & 127;
    int j = g_idx[i];
    float x = X[t];
    float q = C[(size_t)d * NC + j];
    out[t] = x + (q - x);
    float diff = q - x;
    float v = diff * diff;
#pragma unroll
    for (int off = 16; off > 0; off >>= 1)
        v += __shfl_down_sync(0xffffffffu, v, off);
    __shared__ float ws[8];
    int lane = threadIdx.x & 31, w = threadIdx.x >> 5;
    if (lane == 0) ws[w] = v;
    __syncthreads();
    if (threadIdx.x == 0) {
        double s = 0.0;
        for (int k = 0; k < 8; k++) s += (double)ws[k];
        g_partial[blockIdx.x] = s;
    }
}

__global__ void k_loss(float* __restrict__ out, int loss_pos) {
    __shared__ double sm[256];
    double s = 0.0;
    for (int k = threadIdx.x; k < NBLK; k += 256) s += g_partial[k];
    sm[threadIdx.x] = s;
    __syncthreads();
    for (int off = 128; off > 0; off >>= 1) {
        if (threadIdx.x < off) sm[threadIdx.x] += sm[threadIdx.x + off];
        __syncthreads();
    }
    if (threadIdx.x == 0 && loss_pos >= 0)
        out[loss_pos] = (float)(1.25 * sm[0] / (double)NOUT);
}

// ---------------------------------------------------------------------- entry
extern "C" void kernel_launch(void* const* d_in, const int* in_sizes, int n_in,
                              void* d_out, int out_size) {
    const float* X = (const float*)d_in[0];
    const float* C = (const float*)d_in[1];
    if (n_in >= 2 && in_sizes[0] == DD * NC && in_sizes[1] == NOUT) {
        const float* tmp = X; X = C; C = tmp;
    }
    float* out = (float*)d_out;

    static int smem_set = 0;
    if (!smem_set) {
        cudaFuncSetAttribute(k_argmin, cudaFuncAttributeMaxDynamicSharedMemorySize,
                             SMEM_REQ);
        cudaFuncSetAttribute(k_prepB, cudaFuncAttributeMaxDynamicSharedMemorySize,
                             SMEM_PREPB);
        smem_set = 1;
    }

    k_prepB<<<NT, 256, SMEM_PREPB>>>(C);
    k_argmin<<<128, NTHR, SMEM_REQ>>>(X);
    k_rescue<<<128, 128>>>(X, C);
    k_gather<<<NBLK, 256>>>(X, C, out);

    int loss_pos = (out_size > NOUT) ? (out_size - 1) : -1;
    k_loss<<<1, 256>>>(out, loss_pos);
}